// round 16
// baseline (speedup 1.0000x reference)
#include <cuda_runtime.h>
#include <cuda_fp16.h>
#include <cstdint>

// Problem constants
#define L_SEQ 16384
#define H_DIM 1024
#define P_DIM 512
#define N2P   1024        // 2*P
#define KDIM  1024        // K for both GEMMs
#define CHUNK 64
#define HCHUNK 32         // rows per half
#define NCHUNK (L_SEQ / CHUNK)   // 256

// ---------------- device scratch (fp16) ----------------
__device__ __half g_W1[N2P * KDIM];    // weights
__device__ __half g_W2[H_DIM * N2P];
__device__ __half g_uh[L_SEQ * H_DIM]; // activations
__device__ __half g_Bu[L_SEQ * N2P];   // GEMM1 output (fp16)
__device__ __half g_xh[L_SEQ * N2P];
__device__ float2 g_lam[P_DIM];
__device__ float2 g_lampow[P_DIM];     // lam^CHUNK
__device__ float2 g_lam32[P_DIM];      // lam^HCHUNK
__device__ float2 g_carry[NCHUNK * P_DIM];
__device__ int    g_flag[NCHUNK];      // per-chunk aggregate-published flags

// ---------------- helpers ----------------
__device__ __forceinline__ uint32_t smem_u32(const void* p) {
    uint32_t a;
    asm("{ .reg .u64 t; cvta.to.shared.u64 t, %1; cvt.u32.u64 %0, t; }" : "=r"(a) : "l"(p));
    return a;
}
__device__ __forceinline__ void cp_async16(uint32_t dst, const void* src) {
    asm volatile("cp.async.cg.shared.global [%0], [%1], 16;" :: "r"(dst), "l"(src));
}
#define CP_COMMIT() asm volatile("cp.async.commit_group;" ::: "memory")
#define CP_WAIT(n)  asm volatile("cp.async.wait_group %0;" :: "n"(n) : "memory")

__device__ __forceinline__ void ldsm_x4(uint32_t* r, uint32_t addr) {
    asm volatile("ldmatrix.sync.aligned.m8n8.x4.shared.b16 {%0,%1,%2,%3}, [%4];"
        : "=r"(r[0]), "=r"(r[1]), "=r"(r[2]), "=r"(r[3]) : "r"(addr));
}
__device__ __forceinline__ void mma16816(float* d, const uint32_t* a, const uint32_t* b) {
    asm("mma.sync.aligned.m16n8k16.row.col.f32.f16.f16.f32 "
        "{%0,%1,%2,%3}, {%4,%5,%6,%7}, {%8,%9}, {%0,%1,%2,%3};"
        : "+f"(d[0]), "+f"(d[1]), "+f"(d[2]), "+f"(d[3])
        : "r"(a[0]), "r"(a[1]), "r"(a[2]), "r"(a[3]), "r"(b[0]), "r"(b[1]));
}

// ---------------- prep kernels ----------------
__global__ void prep_lambda(const float* __restrict__ Lre,
                            const float* __restrict__ Lim,
                            const float* __restrict__ log_step) {
    int p = threadIdx.x;
    if (p < NCHUNK) g_flag[p] = 0;               // reset lookback flags
    float lr = Lre[p], li = Lim[p];
    float dt = expf(log_step[p]);
    float ar = lr * dt, ai = li * dt;
    float er = expf(ar);
    g_lam[p] = make_float2(er * cosf(ai), er * sinf(ai));
    float eC = expf(ar * (float)CHUNK);
    g_lampow[p] = make_float2(eC * cosf(ai * (float)CHUNK), eC * sinf(ai * (float)CHUNK));
    float eH = expf(ar * (float)HCHUNK);
    g_lam32[p] = make_float2(eH * cosf(ai * (float)HCHUNK), eH * sinf(ai * (float)HCHUNK));
}

// fused: weight prep (blocks 0..2047) + u fp32->fp16 convert (blocks 2048..18431)
#define PREPW_BLOCKS 2048
__global__ void prep_big(const float* __restrict__ B, const float* __restrict__ C,
                         const float* __restrict__ u,
                         const float* __restrict__ Lre, const float* __restrict__ Lim,
                         const float* __restrict__ log_step) {
    int bid = blockIdx.x;
    if (bid < PREPW_BLOCKS) {
        int idx = bid * blockDim.x + threadIdx.x;  // 0 .. P*H-1
        {   // W1 from B: idx = p*H + h
            int p = idx >> 10;
            int h = idx & (H_DIM - 1);
            float lr = Lre[p], li = Lim[p];
            float dt = expf(log_step[p]);
            float ar = lr * dt, ai = li * dt;
            float er = expf(ar);
            float lam_r = er * cosf(ai), lam_i = er * sinf(ai);
            float nr = lam_r - 1.0f, ni = lam_i;
            float den = lr * lr + li * li;
            float gx = (nr * lr + ni * li) / den;
            float gy = (ni * lr - nr * li) / den;
            float2 b = reinterpret_cast<const float2*>(B)[idx];
            float vr = gx * b.x - gy * b.y;
            float vi = gy * b.x + gx * b.y;
            g_W1[p * KDIM + h]           = __float2half_rn(vr);
            g_W1[(P_DIM + p) * KDIM + h] = __float2half_rn(vi);
        }
        {   // W2 from C: idx = h*P + p
            int h = idx >> 9;
            int p = idx & (P_DIM - 1);
            float2 c = reinterpret_cast<const float2*>(C)[idx];
            g_W2[h * N2P + p]         = __float2half_rn(2.0f * c.x);
            g_W2[h * N2P + P_DIM + p] = __float2half_rn(-2.0f * c.y);
        }
    } else {
        int i = (bid - PREPW_BLOCKS) * blockDim.x + threadIdx.x;  // float4 idx
        float4 v = reinterpret_cast<const float4*>(u)[i];
        __half2 a = __floats2half2_rn(v.x, v.y);
        __half2 b = __floats2half2_rn(v.z, v.w);
        uint2 pk = make_uint2(*(uint32_t*)&a, *(uint32_t*)&b);
        reinterpret_cast<uint2*>(g_uh)[i] = pk;
    }
}

// ---------------- mma.sync fp16 GEMM (unchanged control) ----------------
#define BK 64
#define NSTG 3
#define PLANE_B (128 * 128)           // 16384
#define STAGE_B (2 * PLANE_B)         // 32768
#define SMEM_TOT (NSTG * STAGE_B)     // 98304

__device__ __forceinline__ void stage_load(uint32_t sb, int stage,
        const __half* __restrict__ pA, const __half* __restrict__ pB,
        int k0, int tid) {
    uint32_t base = sb + stage * STAGE_B;
#pragma unroll
    for (int i = 0; i < 4; i++) {
        int id = tid + i * 256;               // 0..1023
        int row = id >> 3, ch = id & 7;
        uint32_t dst = base + (uint32_t)(row * 128 + ((ch ^ (row & 7)) << 4));
        size_t gof = (size_t)row * KDIM + k0 + ch * 8;
        cp_async16(dst,           pA + gof);
        cp_async16(dst + PLANE_B, pB + gof);
    }
}

template <bool EPI>
__global__ void __launch_bounds__(256, 2) mma_gemm(
    const __half* __restrict__ A, const __half* __restrict__ Bm,
    void* __restrict__ Co,
    const __half* __restrict__ U, const float* __restrict__ Dv) {
    extern __shared__ __align__(128) char smem[];
    const uint32_t sb = smem_u32(smem);
    const int tid = threadIdx.x;
    const int lane = tid & 31, wid = tid >> 5;
    const int wm = wid & 1, wn = wid >> 1;           // 2x4 warp grid, 64x32 warptile
    const int lq = lane >> 2, lc = lane & 3;
    const int brow = blockIdx.y, bcol = blockIdx.x;

    const __half* pA = A  + (size_t)brow * 128 * KDIM;
    const __half* pB = Bm + (size_t)bcol * 128 * KDIM;

    const int arow = (lane & 7) + ((lane >> 3) & 1) * 8;
    const int akb  = (lane >> 4) & 1;
    const int axor = arow & 7;
    const int brow_l = (lane & 7) + ((lane >> 4) & 1) * 8;
    const int bkb    = (lane >> 3) & 1;
    const int bxor   = brow_l & 7;

    const uint32_t abase = (uint32_t)((wm * 64 + arow) * 128);
    const uint32_t bbase = PLANE_B + (uint32_t)((wn * 32 + brow_l) * 128);

    float acc[4][4][4] = {};
    uint32_t ah[2][4][4], bh[2][2][4];

    stage_load(sb, 0, pA, pB, 0, tid);    CP_COMMIT();
    stage_load(sb, 1, pA, pB, BK, tid);   CP_COMMIT();

    const int NS = KDIM / BK;     // 16
    int sidx = 0;
    for (int s = 0; s < NS; s++) {
        CP_WAIT(1);
        __syncthreads();
        if (s + 2 < NS) {
            int tgt = sidx + 2; if (tgt >= NSTG) tgt -= NSTG;
            stage_load(sb, tgt, pA, pB, (s + 2) * BK, tid);
        }
        CP_COMMIT();

        const uint32_t st = sb + sidx * STAGE_B;

#pragma unroll
        for (int mt = 0; mt < 4; mt++)
            ldsm_x4(ah[0][mt], st + abase + (uint32_t)(mt * 16 * 128)
                               + (uint32_t)((akb ^ axor) << 4));
#pragma unroll
        for (int ntp = 0; ntp < 2; ntp++)
            ldsm_x4(bh[0][ntp], st + bbase + (uint32_t)(ntp * 16 * 128)
                               + (uint32_t)((bkb ^ bxor) << 4));

#pragma unroll
        for (int k16 = 0; k16 < 4; k16++) {
            const int cur = k16 & 1, nxt = cur ^ 1;
            if (k16 < 3) {
                const int kn = k16 + 1;
#pragma unroll
                for (int mt = 0; mt < 4; mt++)
                    ldsm_x4(ah[nxt][mt], st + abase + (uint32_t)(mt * 16 * 128)
                                       + (uint32_t)(((kn * 2 + akb) ^ axor) << 4));
#pragma unroll
                for (int ntp = 0; ntp < 2; ntp++)
                    ldsm_x4(bh[nxt][ntp], st + bbase + (uint32_t)(ntp * 16 * 128)
                                        + (uint32_t)(((kn * 2 + bkb) ^ bxor) << 4));
            }
#pragma unroll
            for (int ntp = 0; ntp < 2; ntp++)
#pragma unroll
                for (int sub = 0; sub < 2; sub++) {
                    const uint32_t* bp = &bh[cur][ntp][sub * 2];
#pragma unroll
                    for (int mt = 0; mt < 4; mt++)
                        mma16816(acc[mt][ntp * 2 + sub], ah[cur][mt], bp);
                }
        }
        sidx++; if (sidx == NSTG) sidx = 0;
    }

    // epilogue
#pragma unroll
    for (int mt = 0; mt < 4; mt++) {
        const int row0 = brow * 128 + wm * 64 + mt * 16 + lq;
#pragma unroll
        for (int nt = 0; nt < 4; nt++) {
            const int col = bcol * 128 + wn * 32 + nt * 8 + lc * 2;
            const float* d = acc[mt][nt];
            if (EPI) {
                float* o = (float*)Co;
                float2 dd = *reinterpret_cast<const float2*>(Dv + col);
                __half2 uh0 = *reinterpret_cast<const __half2*>(U + (size_t)row0 * 1024 + col);
                __half2 uh1 = *reinterpret_cast<const __half2*>(U + (size_t)(row0 + 8) * 1024 + col);
                float2 u0 = __half22float2(uh0);
                float2 u1 = __half22float2(uh1);
                float2 v0 = make_float2(fmaf(dd.x, u0.x, d[0]), fmaf(dd.y, u0.y, d[1]));
                float2 v1 = make_float2(fmaf(dd.x, u1.x, d[2]), fmaf(dd.y, u1.y, d[3]));
                *reinterpret_cast<float2*>(o + (size_t)row0 * 1024 + col) = v0;
                *reinterpret_cast<float2*>(o + (size_t)(row0 + 8) * 1024 + col) = v1;
            } else {
                __half* o = (__half*)Co;
                __half2 h0 = __floats2half2_rn(d[0], d[1]);
                __half2 h1 = __floats2half2_rn(d[2], d[3]);
                *reinterpret_cast<__half2*>(o + (size_t)row0 * 1024 + col) = h0;
                *reinterpret_cast<__half2*>(o + (size_t)(row0 + 8) * 1024 + col) = h1;
            }
        }
    }
}

// ---------------- single-pass scan, two row-halves per block ----------------
// Grid = NCHUNK blocks x 1024 threads. Thread (h, p): h = row-half (32 rows),
// p = state index. Chunk aggregate = lam^32 * b_lo + b_hi (combined via smem).
// All 256 blocks co-resident (2 blocks/SM) -> spin-poll deadlock-free.
__global__ void __launch_bounds__(1024) scan_all() {
    __shared__ float2 s_blo[P_DIM];
    __shared__ float2 s_pref[P_DIM];
    const int c = blockIdx.x;
    const int tid = threadIdx.x;
    const int h = tid >> 9;                 // 0 or 1
    const int p = tid & (P_DIM - 1);
    const float2 lam = g_lam[p];
    const float2 l32 = g_lam32[p];
    const __half* base = g_Bu + (size_t)(c * CHUNK + h * HCHUNK) * N2P;

    // ---- pass 1: local aggregate over 32 rows (batch-8 prefetch)
    float br = 0.f, bi = 0.f;
    for (int g = 0; g < HCHUNK / 8; g++) {
        float ur[8], ui[8];
#pragma unroll
        for (int j = 0; j < 8; j++) {
            ur[j] = __half2float(base[(g * 8 + j) * N2P + p]);
            ui[j] = __half2float(base[(g * 8 + j) * N2P + P_DIM + p]);
        }
#pragma unroll
        for (int j = 0; j < 8; j++) {
            float nr = fmaf(lam.x, br, fmaf(-lam.y, bi, ur[j]));
            float ni = fmaf(lam.x, bi, fmaf(lam.y, br, ui[j]));
            br = nr; bi = ni;
        }
    }
    if (h == 0) s_blo[p] = make_float2(br, bi);
    __syncthreads();
    if (h == 1) {
        float2 lo = s_blo[p];
        float fr = fmaf(l32.x, lo.x, fmaf(-l32.y, lo.y, br));
        float fi = fmaf(l32.x, lo.y, fmaf(l32.y, lo.x, bi));
        g_carry[c * P_DIM + p] = make_float2(fr, fi);
        __threadfence();                    // release carries
    }
    __syncthreads();
    if (tid == 0) atomicExch(&g_flag[c], 1);

    // ---- lookback: all threads poll predecessor flags; h0 computes prefix
    if (c > 0) {
        volatile int* vf = g_flag;
        for (int j = tid; j < c; j += 1024)
            while (vf[j] == 0) {}
        __syncthreads();
        __threadfence();                    // acquire carries
        if (h == 0) {
            const float2 Ap = g_lampow[p];
            float sr = 0.f, si = 0.f;
            for (int j0 = 0; j0 < c; j0 += 4) {
                float2 v[4];
#pragma unroll
                for (int k = 0; k < 4; k++)
                    v[k] = (j0 + k < c) ? g_carry[(j0 + k) * P_DIM + p]
                                        : make_float2(0.f, 0.f);
#pragma unroll
                for (int k = 0; k < 4; k++) {
                    if (j0 + k < c) {
                        float nr = fmaf(Ap.x, sr, fmaf(-Ap.y, si, v[k].x));
                        float ni = fmaf(Ap.x, si, fmaf(Ap.y, sr, v[k].y));
                        sr = nr; si = ni;
                    }
                }
            }
            s_pref[p] = make_float2(sr, si);
        }
        __syncthreads();
    } else {
        if (h == 0) s_pref[p] = make_float2(0.f, 0.f);
        __syncthreads();
    }

    // ---- pass 2: rescan 32 rows with carry-in, write xh
    float2 s = s_pref[p];
    float xr, xi;
    if (h == 0) {
        xr = s.x; xi = s.y;
    } else {
        float2 lo = s_blo[p];               // x_31 = lam^32 * s + b_lo
        xr = fmaf(l32.x, s.x, fmaf(-l32.y, s.y, lo.x));
        xi = fmaf(l32.x, s.y, fmaf(l32.y, s.x, lo.y));
    }
    __half* oh = g_xh + (size_t)(c * CHUNK + h * HCHUNK) * N2P;
    for (int g = 0; g < HCHUNK / 8; g++) {
        float ur[8], ui[8];
#pragma unroll
        for (int j = 0; j < 8; j++) {
            ur[j] = __half2float(base[(g * 8 + j) * N2P + p]);
            ui[j] = __half2float(base[(g * 8 + j) * N2P + P_DIM + p]);
        }
#pragma unroll
        for (int j = 0; j < 8; j++) {
            float nr = fmaf(lam.x, xr, fmaf(-lam.y, xi, ur[j]));
            float ni = fmaf(lam.x, xi, fmaf(lam.y, xr, ui[j]));
            xr = nr; xi = ni;
            oh[(g * 8 + j) * N2P + p]         = __float2half_rn(xr);
            oh[(g * 8 + j) * N2P + P_DIM + p] = __float2half_rn(xi);
        }
    }
}

// ---------------- launcher ----------------
extern "C" void kernel_launch(void* const* d_in, const int* in_sizes, int n_in,
                              void* d_out, int out_size) {
    const float* u        = (const float*)d_in[0];
    const float* Lre      = (const float*)d_in[1];
    const float* Lim      = (const float*)d_in[2];
    const float* B        = (const float*)d_in[3];
    const float* C        = (const float*)d_in[4];
    const float* D        = (const float*)d_in[5];
    const float* log_step = (const float*)d_in[6];
    float* out = (float*)d_out;

    cudaFuncSetAttribute(mma_gemm<false>, cudaFuncAttributeMaxDynamicSharedMemorySize, SMEM_TOT);
    cudaFuncSetAttribute(mma_gemm<true>,  cudaFuncAttributeMaxDynamicSharedMemorySize, SMEM_TOT);

    __half *uh, *w1, *w2, *xh, *bu;
    cudaGetSymbolAddress((void**)&uh, g_uh);
    cudaGetSymbolAddress((void**)&w1, g_W1);
    cudaGetSymbolAddress((void**)&w2, g_W2);
    cudaGetSymbolAddress((void**)&xh, g_xh);
    cudaGetSymbolAddress((void**)&bu, g_Bu);

    prep_lambda<<<1, P_DIM>>>(Lre, Lim, log_step);
    prep_big<<<PREPW_BLOCKS + (L_SEQ * H_DIM / 4) / 256, 256>>>(B, C, u, Lre, Lim, log_step);

    // GEMM1: Bu = u @ W1  (fp16 out)
    mma_gemm<false><<<dim3(N2P / 128, L_SEQ / 128), 256, SMEM_TOT>>>(
        uh, w1, bu, nullptr, nullptr);

    // 4th launch (profiled): fused single-pass scan
    scan_all<<<NCHUNK, 1024>>>();

    // GEMM2: out = xs @ W2 + D .* u
    mma_gemm<true><<<dim3(H_DIM / 128, L_SEQ / 128), 256, SMEM_TOT>>>(
        xh, w2, out, uh, D);
}

// round 17
// speedup vs baseline: 1.0437x; 1.0437x over previous
#include <cuda_runtime.h>
#include <cuda_fp16.h>
#include <cstdint>

// Problem constants
#define L_SEQ 16384
#define H_DIM 1024
#define P_DIM 512
#define N2P   1024        // 2*P
#define KDIM  1024        // K for both GEMMs
#define CHUNK 128
#define HCHUNK 64         // rows per half
#define NCHUNK (L_SEQ / CHUNK)   // 128

// ---------------- device scratch (fp16) ----------------
__device__ __half g_W1[N2P * KDIM];    // weights
__device__ __half g_W2[H_DIM * N2P];
__device__ __half g_uh[L_SEQ * H_DIM]; // activations
__device__ __half g_Bu[L_SEQ * N2P];   // GEMM1 output (fp16)
__device__ __half g_xh[L_SEQ * N2P];
__device__ float2 g_lam[P_DIM];
__device__ float2 g_lampow[P_DIM];     // lam^CHUNK
__device__ float2 g_lamH[P_DIM];       // lam^HCHUNK
__device__ float2 g_carry[NCHUNK * P_DIM];
__device__ int    g_flag[NCHUNK];      // per-chunk aggregate-published flags

// ---------------- helpers ----------------
__device__ __forceinline__ uint32_t smem_u32(const void* p) {
    uint32_t a;
    asm("{ .reg .u64 t; cvta.to.shared.u64 t, %1; cvt.u32.u64 %0, t; }" : "=r"(a) : "l"(p));
    return a;
}
__device__ __forceinline__ void cp_async16(uint32_t dst, const void* src) {
    asm volatile("cp.async.cg.shared.global [%0], [%1], 16;" :: "r"(dst), "l"(src));
}
#define CP_COMMIT() asm volatile("cp.async.commit_group;" ::: "memory")
#define CP_WAIT(n)  asm volatile("cp.async.wait_group %0;" :: "n"(n) : "memory")

__device__ __forceinline__ void ldsm_x4(uint32_t* r, uint32_t addr) {
    asm volatile("ldmatrix.sync.aligned.m8n8.x4.shared.b16 {%0,%1,%2,%3}, [%4];"
        : "=r"(r[0]), "=r"(r[1]), "=r"(r[2]), "=r"(r[3]) : "r"(addr));
}
__device__ __forceinline__ void mma16816(float* d, const uint32_t* a, const uint32_t* b) {
    asm("mma.sync.aligned.m16n8k16.row.col.f32.f16.f16.f32 "
        "{%0,%1,%2,%3}, {%4,%5,%6,%7}, {%8,%9}, {%0,%1,%2,%3};"
        : "+f"(d[0]), "+f"(d[1]), "+f"(d[2]), "+f"(d[3])
        : "r"(a[0]), "r"(a[1]), "r"(a[2]), "r"(a[3]), "r"(b[0]), "r"(b[1]));
}

// ---------------- prep kernels ----------------
__global__ void prep_lambda(const float* __restrict__ Lre,
                            const float* __restrict__ Lim,
                            const float* __restrict__ log_step) {
    int p = threadIdx.x;
    if (p < NCHUNK) g_flag[p] = 0;               // reset lookback flags
    float lr = Lre[p], li = Lim[p];
    float dt = expf(log_step[p]);
    float ar = lr * dt, ai = li * dt;
    float er = expf(ar);
    g_lam[p] = make_float2(er * cosf(ai), er * sinf(ai));
    float eC = expf(ar * (float)CHUNK);
    g_lampow[p] = make_float2(eC * cosf(ai * (float)CHUNK), eC * sinf(ai * (float)CHUNK));
    float eH = expf(ar * (float)HCHUNK);
    g_lamH[p] = make_float2(eH * cosf(ai * (float)HCHUNK), eH * sinf(ai * (float)HCHUNK));
}

// fused: weight prep (blocks 0..2047) + u fp32->fp16 convert (blocks 2048..18431)
#define PREPW_BLOCKS 2048
__global__ void prep_big(const float* __restrict__ B, const float* __restrict__ C,
                         const float* __restrict__ u,
                         const float* __restrict__ Lre, const float* __restrict__ Lim,
                         const float* __restrict__ log_step) {
    int bid = blockIdx.x;
    if (bid < PREPW_BLOCKS) {
        int idx = bid * blockDim.x + threadIdx.x;  // 0 .. P*H-1
        {   // W1 from B: idx = p*H + h
            int p = idx >> 10;
            int h = idx & (H_DIM - 1);
            float lr = Lre[p], li = Lim[p];
            float dt = expf(log_step[p]);
            float ar = lr * dt, ai = li * dt;
            float er = expf(ar);
            float lam_r = er * cosf(ai), lam_i = er * sinf(ai);
            float nr = lam_r - 1.0f, ni = lam_i;
            float den = lr * lr + li * li;
            float gx = (nr * lr + ni * li) / den;
            float gy = (ni * lr - nr * li) / den;
            float2 b = reinterpret_cast<const float2*>(B)[idx];
            float vr = gx * b.x - gy * b.y;
            float vi = gy * b.x + gx * b.y;
            g_W1[p * KDIM + h]           = __float2half_rn(vr);
            g_W1[(P_DIM + p) * KDIM + h] = __float2half_rn(vi);
        }
        {   // W2 from C: idx = h*P + p
            int h = idx >> 9;
            int p = idx & (P_DIM - 1);
            float2 c = reinterpret_cast<const float2*>(C)[idx];
            g_W2[h * N2P + p]         = __float2half_rn(2.0f * c.x);
            g_W2[h * N2P + P_DIM + p] = __float2half_rn(-2.0f * c.y);
        }
    } else {
        int i = (bid - PREPW_BLOCKS) * blockDim.x + threadIdx.x;  // float4 idx
        float4 v = reinterpret_cast<const float4*>(u)[i];
        __half2 a = __floats2half2_rn(v.x, v.y);
        __half2 b = __floats2half2_rn(v.z, v.w);
        uint2 pk = make_uint2(*(uint32_t*)&a, *(uint32_t*)&b);
        reinterpret_cast<uint2*>(g_uh)[i] = pk;
    }
}

// ---------------- mma.sync fp16 GEMM (unchanged control) ----------------
#define BK 64
#define NSTG 3
#define PLANE_B (128 * 128)           // 16384
#define STAGE_B (2 * PLANE_B)         // 32768
#define SMEM_TOT (NSTG * STAGE_B)     // 98304

__device__ __forceinline__ void stage_load(uint32_t sb, int stage,
        const __half* __restrict__ pA, const __half* __restrict__ pB,
        int k0, int tid) {
    uint32_t base = sb + stage * STAGE_B;
#pragma unroll
    for (int i = 0; i < 4; i++) {
        int id = tid + i * 256;               // 0..1023
        int row = id >> 3, ch = id & 7;
        uint32_t dst = base + (uint32_t)(row * 128 + ((ch ^ (row & 7)) << 4));
        size_t gof = (size_t)row * KDIM + k0 + ch * 8;
        cp_async16(dst,           pA + gof);
        cp_async16(dst + PLANE_B, pB + gof);
    }
}

template <bool EPI>
__global__ void __launch_bounds__(256, 2) mma_gemm(
    const __half* __restrict__ A, const __half* __restrict__ Bm,
    void* __restrict__ Co,
    const __half* __restrict__ U, const float* __restrict__ Dv) {
    extern __shared__ __align__(128) char smem[];
    const uint32_t sb = smem_u32(smem);
    const int tid = threadIdx.x;
    const int lane = tid & 31, wid = tid >> 5;
    const int wm = wid & 1, wn = wid >> 1;           // 2x4 warp grid, 64x32 warptile
    const int lq = lane >> 2, lc = lane & 3;
    const int brow = blockIdx.y, bcol = blockIdx.x;

    const __half* pA = A  + (size_t)brow * 128 * KDIM;
    const __half* pB = Bm + (size_t)bcol * 128 * KDIM;

    const int arow = (lane & 7) + ((lane >> 3) & 1) * 8;
    const int akb  = (lane >> 4) & 1;
    const int axor = arow & 7;
    const int brow_l = (lane & 7) + ((lane >> 4) & 1) * 8;
    const int bkb    = (lane >> 3) & 1;
    const int bxor   = brow_l & 7;

    const uint32_t abase = (uint32_t)((wm * 64 + arow) * 128);
    const uint32_t bbase = PLANE_B + (uint32_t)((wn * 32 + brow_l) * 128);

    float acc[4][4][4] = {};
    uint32_t ah[2][4][4], bh[2][2][4];

    stage_load(sb, 0, pA, pB, 0, tid);    CP_COMMIT();
    stage_load(sb, 1, pA, pB, BK, tid);   CP_COMMIT();

    const int NS = KDIM / BK;     // 16
    int sidx = 0;
    for (int s = 0; s < NS; s++) {
        CP_WAIT(1);
        __syncthreads();
        if (s + 2 < NS) {
            int tgt = sidx + 2; if (tgt >= NSTG) tgt -= NSTG;
            stage_load(sb, tgt, pA, pB, (s + 2) * BK, tid);
        }
        CP_COMMIT();

        const uint32_t st = sb + sidx * STAGE_B;

#pragma unroll
        for (int mt = 0; mt < 4; mt++)
            ldsm_x4(ah[0][mt], st + abase + (uint32_t)(mt * 16 * 128)
                               + (uint32_t)((akb ^ axor) << 4));
#pragma unroll
        for (int ntp = 0; ntp < 2; ntp++)
            ldsm_x4(bh[0][ntp], st + bbase + (uint32_t)(ntp * 16 * 128)
                               + (uint32_t)((bkb ^ bxor) << 4));

#pragma unroll
        for (int k16 = 0; k16 < 4; k16++) {
            const int cur = k16 & 1, nxt = cur ^ 1;
            if (k16 < 3) {
                const int kn = k16 + 1;
#pragma unroll
                for (int mt = 0; mt < 4; mt++)
                    ldsm_x4(ah[nxt][mt], st + abase + (uint32_t)(mt * 16 * 128)
                                       + (uint32_t)(((kn * 2 + akb) ^ axor) << 4));
#pragma unroll
                for (int ntp = 0; ntp < 2; ntp++)
                    ldsm_x4(bh[nxt][ntp], st + bbase + (uint32_t)(ntp * 16 * 128)
                                        + (uint32_t)(((kn * 2 + bkb) ^ bxor) << 4));
            }
#pragma unroll
            for (int ntp = 0; ntp < 2; ntp++)
#pragma unroll
                for (int sub = 0; sub < 2; sub++) {
                    const uint32_t* bp = &bh[cur][ntp][sub * 2];
#pragma unroll
                    for (int mt = 0; mt < 4; mt++)
                        mma16816(acc[mt][ntp * 2 + sub], ah[cur][mt], bp);
                }
        }
        sidx++; if (sidx == NSTG) sidx = 0;
    }

    // epilogue
#pragma unroll
    for (int mt = 0; mt < 4; mt++) {
        const int row0 = brow * 128 + wm * 64 + mt * 16 + lq;
#pragma unroll
        for (int nt = 0; nt < 4; nt++) {
            const int col = bcol * 128 + wn * 32 + nt * 8 + lc * 2;
            const float* d = acc[mt][nt];
            if (EPI) {
                float* o = (float*)Co;
                float2 dd = *reinterpret_cast<const float2*>(Dv + col);
                __half2 uh0 = *reinterpret_cast<const __half2*>(U + (size_t)row0 * 1024 + col);
                __half2 uh1 = *reinterpret_cast<const __half2*>(U + (size_t)(row0 + 8) * 1024 + col);
                float2 u0 = __half22float2(uh0);
                float2 u1 = __half22float2(uh1);
                float2 v0 = make_float2(fmaf(dd.x, u0.x, d[0]), fmaf(dd.y, u0.y, d[1]));
                float2 v1 = make_float2(fmaf(dd.x, u1.x, d[2]), fmaf(dd.y, u1.y, d[3]));
                *reinterpret_cast<float2*>(o + (size_t)row0 * 1024 + col) = v0;
                *reinterpret_cast<float2*>(o + (size_t)(row0 + 8) * 1024 + col) = v1;
            } else {
                __half* o = (__half*)Co;
                __half2 h0 = __floats2half2_rn(d[0], d[1]);
                __half2 h1 = __floats2half2_rn(d[2], d[3]);
                *reinterpret_cast<__half2*>(o + (size_t)row0 * 1024 + col) = h0;
                *reinterpret_cast<__half2*>(o + (size_t)(row0 + 8) * 1024 + col) = h1;
            }
        }
    }
}

// ---------------- single-pass scan, two row-halves per block ----------------
// Grid = NCHUNK(128) blocks x 1024 threads. Thread (h, p): h = row-half
// (64 rows), p = state index. Chunk aggregate = lam^64 * b_lo + b_hi.
// All 128 blocks co-resident -> spin-poll deadlock-free.
__global__ void __launch_bounds__(1024) scan_all() {
    __shared__ float2 s_blo[P_DIM];
    __shared__ float2 s_pref[P_DIM];
    const int c = blockIdx.x;
    const int tid = threadIdx.x;
    const int h = tid >> 9;                 // 0 or 1
    const int p = tid & (P_DIM - 1);
    const float2 lam = g_lam[p];
    const float2 lH = g_lamH[p];
    const __half* base = g_Bu + (size_t)(c * CHUNK + h * HCHUNK) * N2P;

    // ---- pass 1: local aggregate over HCHUNK rows (batch-8 prefetch)
    float br = 0.f, bi = 0.f;
    for (int g = 0; g < HCHUNK / 8; g++) {
        float ur[8], ui[8];
#pragma unroll
        for (int j = 0; j < 8; j++) {
            ur[j] = __half2float(base[(g * 8 + j) * N2P + p]);
            ui[j] = __half2float(base[(g * 8 + j) * N2P + P_DIM + p]);
        }
#pragma unroll
        for (int j = 0; j < 8; j++) {
            float nr = fmaf(lam.x, br, fmaf(-lam.y, bi, ur[j]));
            float ni = fmaf(lam.x, bi, fmaf(lam.y, br, ui[j]));
            br = nr; bi = ni;
        }
    }
    if (h == 0) s_blo[p] = make_float2(br, bi);
    __syncthreads();
    if (h == 1) {
        float2 lo = s_blo[p];
        float fr = fmaf(lH.x, lo.x, fmaf(-lH.y, lo.y, br));
        float fi = fmaf(lH.x, lo.y, fmaf(lH.y, lo.x, bi));
        g_carry[c * P_DIM + p] = make_float2(fr, fi);
        __threadfence();                    // release carries
    }
    __syncthreads();
    if (tid == 0) atomicExch(&g_flag[c], 1);

    // ---- lookback: all threads poll predecessor flags; h0 computes prefix
    if (c > 0) {
        volatile int* vf = g_flag;
        for (int j = tid; j < c; j += 1024)
            while (vf[j] == 0) {}
        __syncthreads();
        __threadfence();                    // acquire carries
        if (h == 0) {
            const float2 Ap = g_lampow[p];
            float sr = 0.f, si = 0.f;
            for (int j0 = 0; j0 < c; j0 += 4) {
                float2 v[4];
#pragma unroll
                for (int k = 0; k < 4; k++)
                    v[k] = (j0 + k < c) ? g_carry[(j0 + k) * P_DIM + p]
                                        : make_float2(0.f, 0.f);
#pragma unroll
                for (int k = 0; k < 4; k++) {
                    if (j0 + k < c) {
                        float nr = fmaf(Ap.x, sr, fmaf(-Ap.y, si, v[k].x));
                        float ni = fmaf(Ap.x, si, fmaf(Ap.y, sr, v[k].y));
                        sr = nr; si = ni;
                    }
                }
            }
            s_pref[p] = make_float2(sr, si);
        }
        __syncthreads();
    } else {
        if (h == 0) s_pref[p] = make_float2(0.f, 0.f);
        __syncthreads();
    }

    // ---- pass 2: rescan HCHUNK rows with carry-in, write xh
    float2 s = s_pref[p];
    float xr, xi;
    if (h == 0) {
        xr = s.x; xi = s.y;
    } else {
        float2 lo = s_blo[p];               // carry into half-1 = lam^H * s + b_lo
        xr = fmaf(lH.x, s.x, fmaf(-lH.y, s.y, lo.x));
        xi = fmaf(lH.x, s.y, fmaf(lH.y, s.x, lo.y));
    }
    __half* oh = g_xh + (size_t)(c * CHUNK + h * HCHUNK) * N2P;
    for (int g = 0; g < HCHUNK / 8; g++) {
        float ur[8], ui[8];
#pragma unroll
        for (int j = 0; j < 8; j++) {
            ur[j] = __half2float(base[(g * 8 + j) * N2P + p]);
            ui[j] = __half2float(base[(g * 8 + j) * N2P + P_DIM + p]);
        }
#pragma unroll
        for (int j = 0; j < 8; j++) {
            float nr = fmaf(lam.x, xr, fmaf(-lam.y, xi, ur[j]));
            float ni = fmaf(lam.x, xi, fmaf(lam.y, xr, ui[j]));
            xr = nr; xi = ni;
            oh[(g * 8 + j) * N2P + p]         = __float2half_rn(xr);
            oh[(g * 8 + j) * N2P + P_DIM + p] = __float2half_rn(xi);
        }
    }
}

// ---------------- launcher ----------------
extern "C" void kernel_launch(void* const* d_in, const int* in_sizes, int n_in,
                              void* d_out, int out_size) {
    const float* u        = (const float*)d_in[0];
    const float* Lre      = (const float*)d_in[1];
    const float* Lim      = (const float*)d_in[2];
    const float* B        = (const float*)d_in[3];
    const float* C        = (const float*)d_in[4];
    const float* D        = (const float*)d_in[5];
    const float* log_step = (const float*)d_in[6];
    float* out = (float*)d_out;

    cudaFuncSetAttribute(mma_gemm<false>, cudaFuncAttributeMaxDynamicSharedMemorySize, SMEM_TOT);
    cudaFuncSetAttribute(mma_gemm<true>,  cudaFuncAttributeMaxDynamicSharedMemorySize, SMEM_TOT);

    __half *uh, *w1, *w2, *xh, *bu;
    cudaGetSymbolAddress((void**)&uh, g_uh);
    cudaGetSymbolAddress((void**)&w1, g_W1);
    cudaGetSymbolAddress((void**)&w2, g_W2);
    cudaGetSymbolAddress((void**)&xh, g_xh);
    cudaGetSymbolAddress((void**)&bu, g_Bu);

    prep_lambda<<<1, P_DIM>>>(Lre, Lim, log_step);
    prep_big<<<PREPW_BLOCKS + (L_SEQ * H_DIM / 4) / 256, 256>>>(B, C, u, Lre, Lim, log_step);

    // GEMM1: Bu = u @ W1  (fp16 out)
    mma_gemm<false><<<dim3(N2P / 128, L_SEQ / 128), 256, SMEM_TOT>>>(
        uh, w1, bu, nullptr, nullptr);

    // 4th launch (profiled): fused single-pass scan
    scan_all<<<NCHUNK, 1024>>>();

    // GEMM2: out = xs @ W2 + D .* u
    mma_gemm<true><<<dim3(H_DIM / 128, L_SEQ / 128), 256, SMEM_TOT>>>(
        xh, w2, out, uh, D);
}